// round 3
// baseline (speedup 1.0000x reference)
#include <cuda_runtime.h>

// BiGNNLayer: out = (features + x) @ W1 + b1 + (x * features) @ W2 + b2
// where x = segment_sum(lap_vals[:,None] * features[lap_cols], lap_rows)
//
// R3: CSR build (counting sort) -> FUSED gather-SpMM + dual-GEMM epilogue.
//     No g_x round trip; memory-bound gather and FMA-bound dense overlap
//     across blocks on each SM.
//
// Inputs (metadata order):
//  0: lap_rows int32[E]  1: lap_cols int32[E]  2: lap_vals f32[E]
//  3: features f32[N,64] 4: W1 f32[64,64] 5: b1 f32[64] 6: W2 f32[64,64] 7: b2 f32[64]
// Output: f32 [N, 64]

constexpr int DIM = 64;
constexpr int MAX_NODES = 100000;
constexpr int MAX_EDGES = 3200000;
constexpr int SCAN_BLOCK = 1024;
constexpr int MAX_SCAN_BLOCKS = 128;   // supports N up to 131072

// Static device scratch (no runtime allocation allowed)
__device__ int  g_counts[MAX_NODES];
__device__ int  g_offsets[MAX_NODES];
__device__ int  g_cursor[MAX_NODES];
__device__ int  g_blocksums[MAX_SCAN_BLOCKS];
__device__ int2 g_sorted[MAX_EDGES];    // (col, val-as-int) row-sorted

// ---------------------------------------------------------------------------
// CSR build
// ---------------------------------------------------------------------------
__global__ void zero_counts_kernel(int n) {
    int i = blockIdx.x * blockDim.x + threadIdx.x;
    if (i < n) g_counts[i] = 0;
}

__global__ void hist_kernel(const int4* __restrict__ rows4, int n_edges4) {
    int i = blockIdx.x * blockDim.x + threadIdx.x;
    if (i < n_edges4) {
        int4 r = __ldg(rows4 + i);
        atomicAdd(&g_counts[r.x], 1);
        atomicAdd(&g_counts[r.y], 1);
        atomicAdd(&g_counts[r.z], 1);
        atomicAdd(&g_counts[r.w], 1);
    }
}

__global__ void hist_tail_kernel(const int* __restrict__ rows, int start, int n_edges) {
    int e = start + blockIdx.x * blockDim.x + threadIdx.x;
    if (e < n_edges) atomicAdd(&g_counts[rows[e]], 1);
}

__global__ void scan_block_kernel(int n) {
    __shared__ int s[SCAN_BLOCK];
    int t = threadIdx.x;
    int idx = blockIdx.x * SCAN_BLOCK + t;
    int v = (idx < n) ? g_counts[idx] : 0;
    s[t] = v;
    __syncthreads();
    #pragma unroll
    for (int d = 1; d < SCAN_BLOCK; d <<= 1) {
        int tmp = (t >= d) ? s[t - d] : 0;
        __syncthreads();
        s[t] += tmp;
        __syncthreads();
    }
    if (idx < n) g_offsets[idx] = s[t] - v;                    // exclusive
    if (t == SCAN_BLOCK - 1) g_blocksums[blockIdx.x] = s[t];   // block total
}

__global__ void scan_sums_kernel(int nblk) {
    __shared__ int s[MAX_SCAN_BLOCKS];
    int t = threadIdx.x;
    int v = (t < nblk) ? g_blocksums[t] : 0;
    s[t] = v;
    __syncthreads();
    #pragma unroll
    for (int d = 1; d < MAX_SCAN_BLOCKS; d <<= 1) {
        int tmp = (t >= d) ? s[t - d] : 0;
        __syncthreads();
        s[t] += tmp;
        __syncthreads();
    }
    if (t < nblk) g_blocksums[t] = s[t] - v;
}

__global__ void add_offsets_kernel(int n) {
    int i = blockIdx.x * blockDim.x + threadIdx.x;
    if (i < n) {
        int o = g_offsets[i] + g_blocksums[i >> 10];
        g_offsets[i] = o;
        g_cursor[i] = o;
    }
}

__global__ void scatter_kernel(const int* __restrict__ rows,
                               const int* __restrict__ cols,
                               const float* __restrict__ vals,
                               int n_edges) {
    int e = blockIdx.x * blockDim.x + threadIdx.x;
    if (e >= n_edges) return;
    int r = rows[e];
    int pos = atomicAdd(&g_cursor[r], 1);
    g_sorted[pos] = make_int2(cols[e], __float_as_int(vals[e]));
}

// ---------------------------------------------------------------------------
// Fused gather + dual-GEMM.
// Block = 256 threads (8 warps), 32 nodes/block.
//   Phase 1: warp w gathers rows 4w..4w+3. Lane owns dims {2*lane, 2*lane+1}
//            (one LDG.64 per edge per lane). y1=f+x, y2=f*x -> smem.
//   Phase 2: thread computes 2 nodes x 4 cols of out = y1@W1 + y2@W2 + b.
// ---------------------------------------------------------------------------
constexpr int NPB = 32;       // nodes per block
constexpr int YPAD = 66;      // 64 + 2: float2-aligned, breaks conflicts

__global__ __launch_bounds__(256) void fused_kernel(
        const float2* __restrict__ feat,    // [N, 32] float2 view
        const float*  __restrict__ W1,
        const float*  __restrict__ b1,
        const float*  __restrict__ W2,
        const float*  __restrict__ b2,
        float4* __restrict__ out,
        int n_nodes) {
    __shared__ float y1s[NPB * YPAD];
    __shared__ float y2s[NPB * YPAD];

    int t = threadIdx.x;
    int warp = t >> 5;
    int lane = t & 31;
    int node0 = blockIdx.x * NPB;

    // ---- Phase 1: gather 4 rows per warp ----
    #pragma unroll
    for (int j = 0; j < 4; ++j) {
        int nl = warp * 4 + j;
        int node = node0 + nl;
        float ax = 0.f, ay = 0.f;
        if (node < n_nodes) {
            int off = g_offsets[node];
            int deg = g_counts[node];
            int i = 0;
            for (; i + 4 <= deg; i += 4) {
                int2 p0 = __ldg(&g_sorted[off + i + 0]);
                int2 p1 = __ldg(&g_sorted[off + i + 1]);
                int2 p2 = __ldg(&g_sorted[off + i + 2]);
                int2 p3 = __ldg(&g_sorted[off + i + 3]);
                float2 g0 = __ldg(feat + (size_t)p0.x * 32 + lane);
                float2 g1 = __ldg(feat + (size_t)p1.x * 32 + lane);
                float2 g2 = __ldg(feat + (size_t)p2.x * 32 + lane);
                float2 g3 = __ldg(feat + (size_t)p3.x * 32 + lane);
                float v0 = __int_as_float(p0.y), v1 = __int_as_float(p1.y);
                float v2 = __int_as_float(p2.y), v3 = __int_as_float(p3.y);
                ax += v0 * g0.x; ay += v0 * g0.y;
                ax += v1 * g1.x; ay += v1 * g1.y;
                ax += v2 * g2.x; ay += v2 * g2.y;
                ax += v3 * g3.x; ay += v3 * g3.y;
            }
            for (; i < deg; ++i) {
                int2 p = __ldg(&g_sorted[off + i]);
                float v = __int_as_float(p.y);
                float2 g = __ldg(feat + (size_t)p.x * 32 + lane);
                ax += v * g.x; ay += v * g.y;
            }
            float2 f = __ldg(feat + (size_t)node * 32 + lane);
            y1s[nl * YPAD + 2 * lane]     = f.x + ax;
            y1s[nl * YPAD + 2 * lane + 1] = f.y + ay;
            y2s[nl * YPAD + 2 * lane]     = f.x * ax;
            y2s[nl * YPAD + 2 * lane + 1] = f.y * ay;
        } else {
            y1s[nl * YPAD + 2 * lane]     = 0.f;
            y1s[nl * YPAD + 2 * lane + 1] = 0.f;
            y2s[nl * YPAD + 2 * lane]     = 0.f;
            y2s[nl * YPAD + 2 * lane + 1] = 0.f;
        }
    }
    __syncthreads();

    // ---- Phase 2: dense. thread = 2 nodes x 4 cols ----
    int cg = t & 15;          // col group -> j0 = cg*4
    int ng = t >> 4;          // node group -> n0 = ng*2
    int j0 = cg * 4;
    int n0 = ng * 2;

    float acc[2][4];
    #pragma unroll
    for (int i = 0; i < 2; ++i)
        #pragma unroll
        for (int c = 0; c < 4; ++c) acc[i][c] = 0.f;

    #pragma unroll 8
    for (int k = 0; k < DIM; ++k) {
        float4 w1 = __ldg(reinterpret_cast<const float4*>(W1 + k * DIM + j0));
        float4 w2 = __ldg(reinterpret_cast<const float4*>(W2 + k * DIM + j0));
        #pragma unroll
        for (int i = 0; i < 2; ++i) {
            float a1 = y1s[(n0 + i) * YPAD + k];
            float a2 = y2s[(n0 + i) * YPAD + k];
            acc[i][0] += a1 * w1.x + a2 * w2.x;
            acc[i][1] += a1 * w1.y + a2 * w2.y;
            acc[i][2] += a1 * w1.z + a2 * w2.z;
            acc[i][3] += a1 * w1.w + a2 * w2.w;
        }
    }

    float4 bb;
    bb.x = __ldg(b1 + j0 + 0) + __ldg(b2 + j0 + 0);
    bb.y = __ldg(b1 + j0 + 1) + __ldg(b2 + j0 + 1);
    bb.z = __ldg(b1 + j0 + 2) + __ldg(b2 + j0 + 2);
    bb.w = __ldg(b1 + j0 + 3) + __ldg(b2 + j0 + 3);

    #pragma unroll
    for (int i = 0; i < 2; ++i) {
        int node = node0 + n0 + i;
        if (node < n_nodes) {
            out[(size_t)node * 16 + cg] = make_float4(acc[i][0] + bb.x,
                                                      acc[i][1] + bb.y,
                                                      acc[i][2] + bb.z,
                                                      acc[i][3] + bb.w);
        }
    }
}

// ---------------------------------------------------------------------------
extern "C" void kernel_launch(void* const* d_in, const int* in_sizes, int n_in,
                              void* d_out, int out_size) {
    const int*   rows = (const int*)d_in[0];
    const int*   cols = (const int*)d_in[1];
    const float* vals = (const float*)d_in[2];
    const float* feat = (const float*)d_in[3];
    const float* W1   = (const float*)d_in[4];
    const float* b1   = (const float*)d_in[5];
    const float* W2   = (const float*)d_in[6];
    const float* b2   = (const float*)d_in[7];

    int n_edges = in_sizes[0];
    int n_nodes = in_sizes[3] / DIM;

    // 1) CSR build: histogram -> scan -> scatter
    zero_counts_kernel<<<(n_nodes + 255) / 256, 256>>>(n_nodes);

    int n_e4 = n_edges / 4;
    if (n_e4 > 0)
        hist_kernel<<<(n_e4 + 255) / 256, 256>>>((const int4*)rows, n_e4);
    if (n_edges - n_e4 * 4 > 0)
        hist_tail_kernel<<<1, 256>>>(rows, n_e4 * 4, n_edges);

    int nblk = (n_nodes + SCAN_BLOCK - 1) / SCAN_BLOCK;
    scan_block_kernel<<<nblk, SCAN_BLOCK>>>(n_nodes);
    scan_sums_kernel<<<1, MAX_SCAN_BLOCKS>>>(nblk);
    add_offsets_kernel<<<(n_nodes + 255) / 256, 256>>>(n_nodes);

    scatter_kernel<<<(n_edges + 255) / 256, 256>>>(rows, cols, vals, n_edges);

    // 2) fused gather + dual-GEMM
    fused_kernel<<<(n_nodes + NPB - 1) / NPB, 256>>>(
        (const float2*)feat, W1, b1, W2, b2, (float4*)d_out, n_nodes);
}

// round 4
// speedup vs baseline: 1.0216x; 1.0216x over previous
#include <cuda_runtime.h>

// BiGNNLayer: out = (features + x) @ W1 + b1 + (x * features) @ W2 + b2
// where x = segment_sum(lap_vals[:,None] * features[lap_cols], lap_rows)
//
// R4: R2 structure (CSR build -> warp-per-row gather -> dense epilogue),
//     gather upgraded to float2 loads (LDG.64) + 8-edge unroll,
//     scatter vectorized 4 edges/thread.
//
// Inputs (metadata order):
//  0: lap_rows int32[E]  1: lap_cols int32[E]  2: lap_vals f32[E]
//  3: features f32[N,64] 4: W1 f32[64,64] 5: b1 f32[64] 6: W2 f32[64,64] 7: b2 f32[64]
// Output: f32 [N, 64]

constexpr int DIM = 64;
constexpr int MAX_NODES = 100000;
constexpr int MAX_EDGES = 3200000;
constexpr int SCAN_BLOCK = 1024;
constexpr int MAX_SCAN_BLOCKS = 128;   // supports N up to 131072

// Static device scratch (no runtime allocation allowed)
__device__ int    g_counts[MAX_NODES];
__device__ int    g_offsets[MAX_NODES];
__device__ int    g_cursor[MAX_NODES];
__device__ int    g_blocksums[MAX_SCAN_BLOCKS];
__device__ int2   g_sorted[MAX_EDGES];             // (col, val-as-int) row-sorted
__device__ float2 g_x[MAX_NODES * (DIM / 2)];      // x = L @ features

// ---------------------------------------------------------------------------
// CSR build
// ---------------------------------------------------------------------------
__global__ void zero_counts_kernel(int n) {
    int i = blockIdx.x * blockDim.x + threadIdx.x;
    if (i < n) g_counts[i] = 0;
}

__global__ void hist_kernel(const int4* __restrict__ rows4, int n_edges4) {
    int i = blockIdx.x * blockDim.x + threadIdx.x;
    if (i < n_edges4) {
        int4 r = __ldg(rows4 + i);
        atomicAdd(&g_counts[r.x], 1);
        atomicAdd(&g_counts[r.y], 1);
        atomicAdd(&g_counts[r.z], 1);
        atomicAdd(&g_counts[r.w], 1);
    }
}

__global__ void hist_tail_kernel(const int* __restrict__ rows, int start, int n_edges) {
    int e = start + blockIdx.x * blockDim.x + threadIdx.x;
    if (e < n_edges) atomicAdd(&g_counts[rows[e]], 1);
}

__global__ void scan_block_kernel(int n) {
    __shared__ int s[SCAN_BLOCK];
    int t = threadIdx.x;
    int idx = blockIdx.x * SCAN_BLOCK + t;
    int v = (idx < n) ? g_counts[idx] : 0;
    s[t] = v;
    __syncthreads();
    #pragma unroll
    for (int d = 1; d < SCAN_BLOCK; d <<= 1) {
        int tmp = (t >= d) ? s[t - d] : 0;
        __syncthreads();
        s[t] += tmp;
        __syncthreads();
    }
    if (idx < n) g_offsets[idx] = s[t] - v;                    // exclusive
    if (t == SCAN_BLOCK - 1) g_blocksums[blockIdx.x] = s[t];   // block total
}

__global__ void scan_sums_kernel(int nblk) {
    __shared__ int s[MAX_SCAN_BLOCKS];
    int t = threadIdx.x;
    int v = (t < nblk) ? g_blocksums[t] : 0;
    s[t] = v;
    __syncthreads();
    #pragma unroll
    for (int d = 1; d < MAX_SCAN_BLOCKS; d <<= 1) {
        int tmp = (t >= d) ? s[t - d] : 0;
        __syncthreads();
        s[t] += tmp;
        __syncthreads();
    }
    if (t < nblk) g_blocksums[t] = s[t] - v;
}

__global__ void add_offsets_kernel(int n) {
    int i = blockIdx.x * blockDim.x + threadIdx.x;
    if (i < n) {
        int o = g_offsets[i] + g_blocksums[i >> 10];
        g_offsets[i] = o;
        g_cursor[i] = o;
    }
}

// 4 edges per thread: int4/float4 reads, random int2 stores.
__global__ void scatter_kernel(const int4* __restrict__ rows4,
                               const int4* __restrict__ cols4,
                               const float4* __restrict__ vals4,
                               int n_edges4) {
    int i = blockIdx.x * blockDim.x + threadIdx.x;
    if (i >= n_edges4) return;
    int4   r = __ldg(rows4 + i);
    int4   c = __ldg(cols4 + i);
    float4 v = __ldg(vals4 + i);
    int p0 = atomicAdd(&g_cursor[r.x], 1);
    int p1 = atomicAdd(&g_cursor[r.y], 1);
    int p2 = atomicAdd(&g_cursor[r.z], 1);
    int p3 = atomicAdd(&g_cursor[r.w], 1);
    g_sorted[p0] = make_int2(c.x, __float_as_int(v.x));
    g_sorted[p1] = make_int2(c.y, __float_as_int(v.y));
    g_sorted[p2] = make_int2(c.z, __float_as_int(v.z));
    g_sorted[p3] = make_int2(c.w, __float_as_int(v.w));
}

__global__ void scatter_tail_kernel(const int* __restrict__ rows,
                                    const int* __restrict__ cols,
                                    const float* __restrict__ vals,
                                    int start, int n_edges) {
    int e = start + blockIdx.x * blockDim.x + threadIdx.x;
    if (e >= n_edges) return;
    int r = rows[e];
    int pos = atomicAdd(&g_cursor[r], 1);
    g_sorted[pos] = make_int2(cols[e], __float_as_int(vals[e]));
}

// ---------------------------------------------------------------------------
// Gather SpMM: one warp per destination row. Lane owns dims {2*lane, 2*lane+1}
// -> one LDG.64 per edge per lane, fully coalesced 256B/warp/edge.
// 8-edge unroll keeps 8 independent feature loads in flight per lane.
// ---------------------------------------------------------------------------
__global__ __launch_bounds__(256) void gather_kernel(const float2* __restrict__ feat,
                                                     int n_nodes) {
    int warp = (blockIdx.x * blockDim.x + threadIdx.x) >> 5;
    int lane = threadIdx.x & 31;
    if (warp >= n_nodes) return;

    int off = g_offsets[warp];
    int deg = g_counts[warp];

    float ax = 0.f, ay = 0.f;
    int i = 0;
    for (; i + 8 <= deg; i += 8) {
        int2 p[8];
        #pragma unroll
        for (int u = 0; u < 8; ++u) p[u] = __ldg(&g_sorted[off + i + u]);
        float2 g[8];
        #pragma unroll
        for (int u = 0; u < 8; ++u) g[u] = __ldg(feat + (size_t)p[u].x * 32 + lane);
        #pragma unroll
        for (int u = 0; u < 8; ++u) {
            float v = __int_as_float(p[u].y);
            ax += v * g[u].x;
            ay += v * g[u].y;
        }
    }
    for (; i < deg; ++i) {
        int2 p = __ldg(&g_sorted[off + i]);
        float v = __int_as_float(p.y);
        float2 g = __ldg(feat + (size_t)p.x * 32 + lane);
        ax += v * g.x;
        ay += v * g.y;
    }

    g_x[(size_t)warp * 32 + lane] = make_float2(ax, ay);
}

// ---------------------------------------------------------------------------
// Dense epilogue: block = 64-node tile x 64 cols, 256 threads.
// Thread computes 4 nodes x 4 cols. y tiles staged in padded smem;
// W read via __ldg (32KB, stays hot in L1; feat/x use streaming hint).
// ---------------------------------------------------------------------------
constexpr int YPAD = 68;  // 64 + 4, keeps float4 stores 16B-aligned, breaks conflicts

__global__ __launch_bounds__(256) void dense_kernel(
        const float4* __restrict__ feat,
        const float*  __restrict__ W1,
        const float*  __restrict__ b1,
        const float*  __restrict__ W2,
        const float*  __restrict__ b2,
        float4* __restrict__ out,
        int n_nodes) {
    __shared__ float y1s[64 * YPAD];
    __shared__ float y2s[64 * YPAD];

    int t = threadIdx.x;
    int node0 = blockIdx.x * 64;

    const float4* x4 = reinterpret_cast<const float4*>(g_x);

    // Stage y1 = f + x, y2 = f * x for 64 nodes (coalesced float4 loads).
    #pragma unroll
    for (int q = 0; q < 4; ++q) {
        int idx = q * 256 + t;           // 0..1023
        int nl = idx >> 4;               // local node 0..63
        int k4 = idx & 15;               // float4 chunk 0..15
        int node = node0 + nl;
        float4 f = make_float4(0.f, 0.f, 0.f, 0.f);
        float4 x = make_float4(0.f, 0.f, 0.f, 0.f);
        if (node < n_nodes) {
            f = __ldcs(feat + (size_t)node * 16 + k4);
            x = __ldcs(x4 + (size_t)node * 16 + k4);
        }
        float* p1 = &y1s[nl * YPAD + k4 * 4];
        float* p2 = &y2s[nl * YPAD + k4 * 4];
        p1[0] = f.x + x.x; p1[1] = f.y + x.y; p1[2] = f.z + x.z; p1[3] = f.w + x.w;
        p2[0] = f.x * x.x; p2[1] = f.y * x.y; p2[2] = f.z * x.z; p2[3] = f.w * x.w;
    }
    __syncthreads();

    int cg = t & 15;         // col group: j0 = cg*4
    int ng = t >> 4;         // node group: n0 = ng*4
    int j0 = cg * 4;
    int n0 = ng * 4;

    float acc[4][4];
    #pragma unroll
    for (int i = 0; i < 4; ++i)
        #pragma unroll
        for (int c = 0; c < 4; ++c) acc[i][c] = 0.f;

    #pragma unroll 8
    for (int k = 0; k < DIM; ++k) {
        float4 w1 = __ldg(reinterpret_cast<const float4*>(W1 + k * DIM + j0));
        float4 w2 = __ldg(reinterpret_cast<const float4*>(W2 + k * DIM + j0));
        #pragma unroll
        for (int i = 0; i < 4; ++i) {
            float a1 = y1s[(n0 + i) * YPAD + k];   // broadcast across 16 lanes
            float a2 = y2s[(n0 + i) * YPAD + k];
            acc[i][0] += a1 * w1.x + a2 * w2.x;
            acc[i][1] += a1 * w1.y + a2 * w2.y;
            acc[i][2] += a1 * w1.z + a2 * w2.z;
            acc[i][3] += a1 * w1.w + a2 * w2.w;
        }
    }

    float4 bb;
    bb.x = __ldg(b1 + j0 + 0) + __ldg(b2 + j0 + 0);
    bb.y = __ldg(b1 + j0 + 1) + __ldg(b2 + j0 + 1);
    bb.z = __ldg(b1 + j0 + 2) + __ldg(b2 + j0 + 2);
    bb.w = __ldg(b1 + j0 + 3) + __ldg(b2 + j0 + 3);

    #pragma unroll
    for (int i = 0; i < 4; ++i) {
        int node = node0 + n0 + i;
        if (node < n_nodes) {
            out[(size_t)node * 16 + cg] = make_float4(acc[i][0] + bb.x,
                                                      acc[i][1] + bb.y,
                                                      acc[i][2] + bb.z,
                                                      acc[i][3] + bb.w);
        }
    }
}

// ---------------------------------------------------------------------------
extern "C" void kernel_launch(void* const* d_in, const int* in_sizes, int n_in,
                              void* d_out, int out_size) {
    const int*   rows = (const int*)d_in[0];
    const int*   cols = (const int*)d_in[1];
    const float* vals = (const float*)d_in[2];
    const float* feat = (const float*)d_in[3];
    const float* W1   = (const float*)d_in[4];
    const float* b1   = (const float*)d_in[5];
    const float* W2   = (const float*)d_in[6];
    const float* b2   = (const float*)d_in[7];

    int n_edges = in_sizes[0];
    int n_nodes = in_sizes[3] / DIM;

    // 1) CSR build: histogram -> scan -> scatter
    zero_counts_kernel<<<(n_nodes + 255) / 256, 256>>>(n_nodes);

    int n_e4 = n_edges / 4;
    if (n_e4 > 0)
        hist_kernel<<<(n_e4 + 255) / 256, 256>>>((const int4*)rows, n_e4);
    if (n_edges - n_e4 * 4 > 0)
        hist_tail_kernel<<<1, 256>>>(rows, n_e4 * 4, n_edges);

    int nblk = (n_nodes + SCAN_BLOCK - 1) / SCAN_BLOCK;
    scan_block_kernel<<<nblk, SCAN_BLOCK>>>(n_nodes);
    scan_sums_kernel<<<1, MAX_SCAN_BLOCKS>>>(nblk);
    add_offsets_kernel<<<(n_nodes + 255) / 256, 256>>>(n_nodes);

    if (n_e4 > 0)
        scatter_kernel<<<(n_e4 + 255) / 256, 256>>>(
            (const int4*)rows, (const int4*)cols, (const float4*)vals, n_e4);
    if (n_edges - n_e4 * 4 > 0)
        scatter_tail_kernel<<<1, 256>>>(rows, cols, vals, n_e4 * 4, n_edges);

    // 2) atomic-free gather SpMM: one warp per row
    long long threads = (long long)n_nodes * 32;
    gather_kernel<<<(int)((threads + 255) / 256), 256>>>(
        (const float2*)feat, n_nodes);

    // 3) dense epilogue
    dense_kernel<<<(n_nodes + 63) / 64, 256>>>((const float4*)feat, W1, b1,
                                               W2, b2, (float4*)d_out, n_nodes);
}